// round 3
// baseline (speedup 1.0000x reference)
#include <cuda_runtime.h>

#define NN 50000
#define EE 800000
#define HD 128

// Scratch (device globals — no allocations allowed)
__device__ __align__(256) float g_h[NN * HD];     // GEMM output (dinv-scaled)
__device__ __align__(256) float g_buf[NN * HD];   // layer input ping buffer
__device__ float g_dinv[NN];
__device__ int   g_cnt[NN];
__device__ int   g_cur[NN];
__device__ int   g_off[NN + 1];
__device__ int   g_csr[EE];
__device__ int   g_bsum[64];
__device__ int   g_boff[64];
__device__ int   g_is64;          // 1 if edge_index is int64, 0 if int32

// ---------------- dtype detection ----------------
// int64 node ids < 2^31 => int32 view has zeros at all odd positions.
// For real int32 data those positions are random node ids (P(all 0) ~ 0).

__global__ void k_detect(const int* __restrict__ ei32) {
    if (threadIdx.x == 0) {
        int any = 0;
        for (int i = 0; i < 512; i++) any |= ei32[2 * i + 1];
        g_is64 = (any == 0) ? 1 : 0;
    }
}

__device__ __forceinline__ int edge_at(const void* ei, int pos) {
    if (g_is64) return (int)((const long long*)ei)[pos];
    return ((const int*)ei)[pos];
}

// ---------------- graph preprocessing ----------------

__global__ void k_init(int n) {
    int i = blockIdx.x * blockDim.x + threadIdx.x;
    if (i < n) { g_cnt[i] = 0; g_cur[i] = 0; }
}

__global__ void k_hist(const void* __restrict__ ei, int e, int n) {
    int i = blockIdx.x * blockDim.x + threadIdx.x;
    if (i < e) {
        int d = edge_at(ei, e + i);
        if ((unsigned)d < (unsigned)n) atomicAdd(&g_cnt[d], 1);
    }
}

__global__ void k_scan1(int n) {
    __shared__ int s[1024];
    int i = blockIdx.x * 1024 + threadIdx.x;
    int v = (i < n) ? g_cnt[i] : 0;
    s[threadIdx.x] = v;
    __syncthreads();
    for (int d = 1; d < 1024; d <<= 1) {
        int t = (threadIdx.x >= (unsigned)d) ? s[threadIdx.x - d] : 0;
        __syncthreads();
        s[threadIdx.x] += t;
        __syncthreads();
    }
    if (i < n) g_off[i] = s[threadIdx.x] - v;          // exclusive
    if (threadIdx.x == 1023) g_bsum[blockIdx.x] = s[1023];
}

__global__ void k_scan2(int nb, int n) {
    __shared__ int s[1024];
    int v = (threadIdx.x < (unsigned)nb) ? g_bsum[threadIdx.x] : 0;
    s[threadIdx.x] = v;
    __syncthreads();
    for (int d = 1; d < 1024; d <<= 1) {
        int t = (threadIdx.x >= (unsigned)d) ? s[threadIdx.x - d] : 0;
        __syncthreads();
        s[threadIdx.x] += t;
        __syncthreads();
    }
    if (threadIdx.x < (unsigned)nb) g_boff[threadIdx.x] = s[threadIdx.x] - v;
    if (threadIdx.x == 1023) g_off[n] = s[1023];       // total = E
}

__global__ void k_scan3(int n) {
    int i = blockIdx.x * 1024 + threadIdx.x;
    if (i < n) g_off[i] += g_boff[blockIdx.x];
}

__global__ void k_dinv(int n) {
    int i = blockIdx.x * blockDim.x + threadIdx.x;
    if (i < n) g_dinv[i] = rsqrtf((float)(g_cnt[i] + 1));  // +1 self loop
}

__global__ void k_scatter(const void* __restrict__ ei, int e, int n) {
    int i = blockIdx.x * blockDim.x + threadIdx.x;
    if (i < e) {
        int s = edge_at(ei, i);
        int d = edge_at(ei, e + i);
        if ((unsigned)s < (unsigned)n && (unsigned)d < (unsigned)n) {
            int p = g_off[d] + atomicAdd(&g_cur[d], 1);
            g_csr[p] = s;
        }
    }
}

// ---------------- GEMM: g_h[r] = dinv[r] * (in[r] @ W) ----------------
// block = 256 threads, tile 64 rows x 128 cols, K chunked by 64.
// Static shared: 32KB (W chunk) + 16KB (X chunk) = 48KB exactly.

__global__ void __launch_bounds__(256)
k_gemm(const float* __restrict__ in, const float* __restrict__ W,
       int in_is_gbuf, int n) {
    __shared__ float Ws[64 * 128];   // [k][n] chunk
    __shared__ float Xs[64 * 64];    // [row][k] chunk

    const float* __restrict__ src = in_is_gbuf ? g_buf : in;

    int tid = threadIdx.x;
    int row0 = blockIdx.x * 64;

    int ty = tid >> 4;       // 0..15 -> rows ty*4 .. ty*4+3
    int tx = tid & 15;       // 0..15 -> cols tx*8 .. tx*8+7
    int tx8 = tx * 8;
    int ty4 = ty * 4;

    float4 acc[4][2];
#pragma unroll
    for (int i = 0; i < 4; i++)
        for (int j = 0; j < 2; j++)
            acc[i][j] = make_float4(0.f, 0.f, 0.f, 0.f);

    for (int kc = 0; kc < 2; kc++) {
        if (kc) __syncthreads();     // protect previous-iter reads

        // stage W chunk: rows kc*64..kc*64+63 of W (contiguous 8192 floats)
        for (int i = tid * 4; i < 64 * 128; i += 256 * 4)
            *(float4*)&Ws[i] = *(const float4*)&W[kc * 8192 + i];

        // stage X chunk: rows row0..row0+63, cols kc*64..kc*64+63
        for (int i = tid * 4; i < 64 * 64; i += 256 * 4) {
            int r = i >> 6, c = i & 63;
            int gr = row0 + r;
            *(float4*)&Xs[i] = (gr < n)
                ? *(const float4*)&src[gr * 128 + kc * 64 + c]
                : make_float4(0.f, 0.f, 0.f, 0.f);
        }
        __syncthreads();

#pragma unroll 4
        for (int k = 0; k < 64; k++) {
            float4 w0 = *(float4*)&Ws[k * 128 + tx8];
            float4 w1 = *(float4*)&Ws[k * 128 + tx8 + 4];
            float xv[4];
#pragma unroll
            for (int i = 0; i < 4; i++) xv[i] = Xs[(ty4 + i) * 64 + k];
#pragma unroll
            for (int i = 0; i < 4; i++) {
                acc[i][0].x = fmaf(xv[i], w0.x, acc[i][0].x);
                acc[i][0].y = fmaf(xv[i], w0.y, acc[i][0].y);
                acc[i][0].z = fmaf(xv[i], w0.z, acc[i][0].z);
                acc[i][0].w = fmaf(xv[i], w0.w, acc[i][0].w);
                acc[i][1].x = fmaf(xv[i], w1.x, acc[i][1].x);
                acc[i][1].y = fmaf(xv[i], w1.y, acc[i][1].y);
                acc[i][1].z = fmaf(xv[i], w1.z, acc[i][1].z);
                acc[i][1].w = fmaf(xv[i], w1.w, acc[i][1].w);
            }
        }
    }

#pragma unroll
    for (int i = 0; i < 4; i++) {
        int gr = row0 + ty4 + i;
        if (gr < n) {
            float dv = g_dinv[gr];
            float4 a0 = acc[i][0], a1 = acc[i][1];
            a0.x *= dv; a0.y *= dv; a0.z *= dv; a0.w *= dv;
            a1.x *= dv; a1.y *= dv; a1.z *= dv; a1.w *= dv;
            *(float4*)&g_h[gr * 128 + tx8]     = a0;
            *(float4*)&g_h[gr * 128 + tx8 + 4] = a1;
        }
    }
}

// ---------------- Aggregation: warp per node, register accumulators ----------------
// dst[v] = dinv[v]*(g_h[v] + sum_{e:dst=v} g_h[src]) + b   (optional relu)

__global__ void k_agg(const float* __restrict__ bias, float* __restrict__ out,
                      int out_is_gbuf, int n, int do_relu) {
    int w = (blockIdx.x * blockDim.x + threadIdx.x) >> 5;
    int lane = threadIdx.x & 31;
    if (w >= n) return;

    float* __restrict__ dst = out_is_gbuf ? g_buf : out;

    const float4* hv = (const float4*)g_h;
    float4 acc = hv[w * 32 + lane];                    // self loop term
    int beg = g_off[w], end = g_off[w + 1];
    for (int j = beg; j < end; j++) {
        int s = g_csr[j];
        float4 m = hv[s * 32 + lane];
        acc.x += m.x; acc.y += m.y; acc.z += m.z; acc.w += m.w;
    }
    float dv = g_dinv[w];
    float4 bb = ((const float4*)bias)[lane];
    acc.x = fmaf(acc.x, dv, bb.x);
    acc.y = fmaf(acc.y, dv, bb.y);
    acc.z = fmaf(acc.z, dv, bb.z);
    acc.w = fmaf(acc.w, dv, bb.w);
    if (do_relu) {
        acc.x = fmaxf(acc.x, 0.f); acc.y = fmaxf(acc.y, 0.f);
        acc.z = fmaxf(acc.z, 0.f); acc.w = fmaxf(acc.w, 0.f);
    }
    ((float4*)dst)[w * 32 + lane] = acc;
}

// ---------------- launch ----------------

extern "C" void kernel_launch(void* const* d_in, const int* in_sizes, int n_in,
                              void* d_out, int out_size) {
    const float* x  = (const float*)d_in[0];
    const void*  ei = d_in[1];
    const float* W1 = (const float*)d_in[2];
    const float* b1 = (const float*)d_in[3];
    const float* W2 = (const float*)d_in[4];
    const float* b2 = (const float*)d_in[5];
    const float* W3 = (const float*)d_in[6];
    const float* b3 = (const float*)d_in[7];
    float* out = (float*)d_out;

    int n = in_sizes[0] / HD;     // 50000
    int e = in_sizes[1] / 2;      // 800000

    int nb = (n + 1023) / 1024;

    k_detect<<<1, 32>>>((const int*)ei);
    k_init<<<(n + 255) / 256, 256>>>(n);
    k_hist<<<(e + 255) / 256, 256>>>(ei, e, n);
    k_scan1<<<nb, 1024>>>(n);
    k_scan2<<<1, 1024>>>(nb, n);
    k_scan3<<<nb, 1024>>>(n);
    k_dinv<<<(n + 255) / 256, 256>>>(n);
    k_scatter<<<(e + 255) / 256, 256>>>(ei, e, n);

    int gemm_blocks = (n + 63) / 64;
    int agg_blocks  = (n * 32 + 255) / 256;

    // layer 1: x -> g_h -> g_buf (relu)
    k_gemm<<<gemm_blocks, 256>>>(x, W1, 0, n);
    k_agg <<<agg_blocks, 256>>>(b1, nullptr, 1, n, 1);
    // layer 2: g_buf -> g_h -> g_buf (relu)
    k_gemm<<<gemm_blocks, 256>>>(nullptr, W2, 1, n);
    k_agg <<<agg_blocks, 256>>>(b2, nullptr, 1, n, 1);
    // layer 3: g_buf -> g_h -> out
    k_gemm<<<gemm_blocks, 256>>>(nullptr, W3, 1, n);
    k_agg <<<agg_blocks, 256>>>(b3, out, 0, n, 0);
}